// round 2
// baseline (speedup 1.0000x reference)
#include <cuda_runtime.h>
#include <math.h>

// out[b,l,c,e] = A[e] + ds * Bv[e]
//   ds = valid ? mat2[row, c] : 0
//   A[e]  = esl[m][e] + (etl[m][e]*(TU - t) + etu[m][e]*t) / TU
//   Bv[e] = (esu[m][e] - esl[m][e]) / SU
// SU=500, TU=3600 (SL=TL=0)

__global__ void __launch_bounds__(256) embed_kernel(
    const int*   __restrict__ traj_loc,   // (B*L)
    const float* __restrict__ mat2,       // (LOC, LOC)
    const float* __restrict__ vec,        // (B*L)
    const int*   __restrict__ traj_len,   // (B)
    const float* __restrict__ emb_sl,     // (2, E)
    const float* __restrict__ emb_su,
    const float* __restrict__ emb_tl,
    const float* __restrict__ emb_tu,
    float*       __restrict__ out,        // (B, L, LOC, E)
    int L, int LOC, int E)
{
    const int bl = blockIdx.x;
    const int b  = bl / L;
    const int l  = bl - b * L;

    const bool valid = (l < traj_len[b]);
    const int  m     = valid ? 1 : 0;
    const float t    = vec[bl];

    int row = traj_loc[bl] - 1;
    row = row < 0 ? 0 : (row > LOC - 1 ? LOC - 1 : row);

    const int EQ = E >> 2;                 // float4 groups per c (E=16 -> 4)
    const int q  = threadIdx.x & (EQ - 1); // this thread's e-group (stride 256 % EQ == 0)

    const float4 esl = reinterpret_cast<const float4*>(emb_sl + m * E)[q];
    const float4 esu = reinterpret_cast<const float4*>(emb_su + m * E)[q];
    const float4 etl = reinterpret_cast<const float4*>(emb_tl + m * E)[q];
    const float4 etu = reinterpret_cast<const float4*>(emb_tu + m * E)[q];

    const float invS = 1.0f / 500.0f;   // 1/(SU-SL)
    const float invT = 1.0f / 3600.0f;  // 1/(TU-TL)
    const float TUv  = 3600.0f;

    float4 A, Bv;
    A.x = fmaf(fmaf(etl.x, TUv - t, etu.x * t), invT, esl.x);
    A.y = fmaf(fmaf(etl.y, TUv - t, etu.y * t), invT, esl.y);
    A.z = fmaf(fmaf(etl.z, TUv - t, etu.z * t), invT, esl.z);
    A.w = fmaf(fmaf(etl.w, TUv - t, etu.w * t), invT, esl.w);
    Bv.x = (esu.x - esl.x) * invS;
    Bv.y = (esu.y - esl.y) * invS;
    Bv.z = (esu.z - esl.z) * invS;
    Bv.w = (esu.w - esl.w) * invS;

    const float* __restrict__ mrow = mat2 + (size_t)row * LOC;
    float4* __restrict__ o = reinterpret_cast<float4*>(out + (size_t)bl * LOC * E);

    const int n4 = LOC * EQ;  // float4 elements per (b,l) tile
    if (valid) {
        #pragma unroll 4
        for (int i = threadIdx.x; i < n4; i += 256) {
            const int c = i / EQ;
            const float ds = __ldg(mrow + c);
            float4 v;
            v.x = fmaf(ds, Bv.x, A.x);
            v.y = fmaf(ds, Bv.y, A.y);
            v.z = fmaf(ds, Bv.z, A.z);
            v.w = fmaf(ds, Bv.w, A.w);
            o[i] = v;
        }
    } else {
        #pragma unroll 4
        for (int i = threadIdx.x; i < n4; i += 256) {
            o[i] = A;  // ds == 0
        }
    }
}

extern "C" void kernel_launch(void* const* d_in, const int* in_sizes, int n_in,
                              void* d_out, int out_size)
{
    const int*   traj_loc = (const int*)  d_in[0];
    const float* mat2     = (const float*)d_in[1];
    const float* vec      = (const float*)d_in[2];
    const int*   traj_len = (const int*)  d_in[3];
    const float* emb_sl   = (const float*)d_in[4];
    const float* emb_su   = (const float*)d_in[5];
    const float* emb_tl   = (const float*)d_in[6];
    const float* emb_tu   = (const float*)d_in[7];

    const int BL  = in_sizes[0];                       // B*L
    const int B   = in_sizes[3];
    const int L   = BL / B;
    const int LOC = (int)(sqrt((double)in_sizes[1]) + 0.5);
    const int E   = in_sizes[4] / 2;

    embed_kernel<<<BL, 256>>>(traj_loc, mat2, vec, traj_len,
                              emb_sl, emb_su, emb_tl, emb_tu,
                              (float*)d_out, L, LOC, E);
}

// round 3
// speedup vs baseline: 1.0222x; 1.0222x over previous
#include <cuda_runtime.h>
#include <math.h>

// out[b,l,c,e] = A[e] + ds * Bv[e]
//   ds = valid ? mat2[row, c] : 0
//   A[e]  = esl[m][e] + (etl[m][e]*(TU - t) + etu[m][e]*t) / TU
//   Bv[e] = (esu[m][e] - esl[m][e]) / SU
// SU=500, TU=3600 (SL=TL=0)

__global__ void __launch_bounds__(256) embed_kernel(
    const int*   __restrict__ traj_loc,   // (B*L)
    const float* __restrict__ mat2,       // (LOC, LOC)
    const float* __restrict__ vec,        // (B*L)
    const int*   __restrict__ traj_len,   // (B)
    const float* __restrict__ emb_sl,     // (2, E)
    const float* __restrict__ emb_su,
    const float* __restrict__ emb_tl,
    const float* __restrict__ emb_tu,
    float*       __restrict__ out,        // (B, L, LOC, E)
    int L, int LOC, int E)
{
    const int bl = blockIdx.x;
    const int b  = bl / L;
    const int l  = bl - b * L;

    const bool valid = (l < traj_len[b]);
    const int  m     = valid ? 1 : 0;
    const float t    = vec[bl];

    int row = traj_loc[bl] - 1;
    row = row < 0 ? 0 : (row > LOC - 1 ? LOC - 1 : row);

    const int EQ = E >> 2;                 // float4 groups per c (E=16 -> 4)
    const int q  = threadIdx.x & (EQ - 1); // this thread's e-group (stride 256 % EQ == 0)

    const float4 esl = reinterpret_cast<const float4*>(emb_sl + m * E)[q];
    const float4 esu = reinterpret_cast<const float4*>(emb_su + m * E)[q];
    const float4 etl = reinterpret_cast<const float4*>(emb_tl + m * E)[q];
    const float4 etu = reinterpret_cast<const float4*>(emb_tu + m * E)[q];

    const float invS = 1.0f / 500.0f;   // 1/(SU-SL)
    const float invT = 1.0f / 3600.0f;  // 1/(TU-TL)
    const float TUv  = 3600.0f;

    float4 A, Bv;
    A.x = fmaf(fmaf(etl.x, TUv - t, etu.x * t), invT, esl.x);
    A.y = fmaf(fmaf(etl.y, TUv - t, etu.y * t), invT, esl.y);
    A.z = fmaf(fmaf(etl.z, TUv - t, etu.z * t), invT, esl.z);
    A.w = fmaf(fmaf(etl.w, TUv - t, etu.w * t), invT, esl.w);
    Bv.x = (esu.x - esl.x) * invS;
    Bv.y = (esu.y - esl.y) * invS;
    Bv.z = (esu.z - esl.z) * invS;
    Bv.w = (esu.w - esl.w) * invS;

    const float* __restrict__ mrow = mat2 + (size_t)row * LOC;
    float4* __restrict__ o = reinterpret_cast<float4*>(out + (size_t)bl * LOC * E);

    const int n4 = LOC * EQ;  // float4 elements per (b,l) tile
    if (valid) {
        #pragma unroll 4
        for (int i = threadIdx.x; i < n4; i += 256) {
            const int c = i / EQ;
            const float ds = __ldg(mrow + c);
            float4 v;
            v.x = fmaf(ds, Bv.x, A.x);
            v.y = fmaf(ds, Bv.y, A.y);
            v.z = fmaf(ds, Bv.z, A.z);
            v.w = fmaf(ds, Bv.w, A.w);
            o[i] = v;
        }
    } else {
        #pragma unroll 4
        for (int i = threadIdx.x; i < n4; i += 256) {
            o[i] = A;  // ds == 0
        }
    }
}

extern "C" void kernel_launch(void* const* d_in, const int* in_sizes, int n_in,
                              void* d_out, int out_size)
{
    const int*   traj_loc = (const int*)  d_in[0];
    const float* mat2     = (const float*)d_in[1];
    const float* vec      = (const float*)d_in[2];
    const int*   traj_len = (const int*)  d_in[3];
    const float* emb_sl   = (const float*)d_in[4];
    const float* emb_su   = (const float*)d_in[5];
    const float* emb_tl   = (const float*)d_in[6];
    const float* emb_tu   = (const float*)d_in[7];

    const int BL  = in_sizes[0];                       // B*L
    const int B   = in_sizes[3];
    const int L   = BL / B;
    const int LOC = (int)(sqrt((double)in_sizes[1]) + 0.5);
    const int E   = in_sizes[4] / 2;

    embed_kernel<<<BL, 256>>>(traj_loc, mat2, vec, traj_len,
                              emb_sl, emb_su, emb_tl, emb_tu,
                              (float*)d_out, L, LOC, E);
}

// round 4
// speedup vs baseline: 1.3169x; 1.2883x over previous
#include <cuda_runtime.h>
#include <math.h>

// out[b,l,c,e] = A[e] + ds * Bv[e]
//   ds = valid ? mat2[row, c] : 0
//   A[e]  = esl[m][e] + (etl[m][e]*(TU - t) + etu[m][e]*t) / TU
//   Bv[e] = (esu[m][e] - esl[m][e]) / SU
// SU=500, TU=3600 (SL=TL=0)

__device__ __forceinline__ void compute_coeffs(
    const float* __restrict__ emb_sl, const float* __restrict__ emb_su,
    const float* __restrict__ emb_tl, const float* __restrict__ emb_tu,
    int m, int E, int q, float t, float4& A, float4& Bv)
{
    const float4 esl = reinterpret_cast<const float4*>(emb_sl + m * E)[q];
    const float4 esu = reinterpret_cast<const float4*>(emb_su + m * E)[q];
    const float4 etl = reinterpret_cast<const float4*>(emb_tl + m * E)[q];
    const float4 etu = reinterpret_cast<const float4*>(emb_tu + m * E)[q];

    const float invS = 1.0f / 500.0f;
    const float invT = 1.0f / 3600.0f;
    const float TUv  = 3600.0f;

    A.x = fmaf(fmaf(etl.x, TUv - t, etu.x * t), invT, esl.x);
    A.y = fmaf(fmaf(etl.y, TUv - t, etu.y * t), invT, esl.y);
    A.z = fmaf(fmaf(etl.z, TUv - t, etu.z * t), invT, esl.z);
    A.w = fmaf(fmaf(etl.w, TUv - t, etu.w * t), invT, esl.w);
    Bv.x = (esu.x - esl.x) * invS;
    Bv.y = (esu.y - esl.y) * invS;
    Bv.z = (esu.z - esl.z) * invS;
    Bv.w = (esu.w - esl.w) * invS;
}

// Fast path: E == 16 (EQ = 4, c = i >> 2)
__global__ void __launch_bounds__(256) embed_kernel_e16(
    const int*   __restrict__ traj_loc,
    const float* __restrict__ mat2,
    const float* __restrict__ vec,
    const int*   __restrict__ traj_len,
    const float* __restrict__ emb_sl,
    const float* __restrict__ emb_su,
    const float* __restrict__ emb_tl,
    const float* __restrict__ emb_tu,
    float*       __restrict__ out,
    int L, int LOC)
{
    const int bl = blockIdx.x;
    const int b  = bl / L;
    const int l  = bl - b * L;

    const bool valid = (l < traj_len[b]);
    const int  m     = valid ? 1 : 0;
    const float t    = vec[bl];

    int row = traj_loc[bl] - 1;
    row = row < 0 ? 0 : (row > LOC - 1 ? LOC - 1 : row);

    const int q = threadIdx.x & 3;
    float4 A, Bv;
    compute_coeffs(emb_sl, emb_su, emb_tl, emb_tu, m, 16, q, t, A, Bv);

    const float* __restrict__ mrow = mat2 + (size_t)row * LOC;
    float4* __restrict__ o = reinterpret_cast<float4*>(out + (size_t)bl * LOC * 16);

    const int n4 = LOC * 4;               // float4 elems per tile (8000)
    const int tid = threadIdx.x;

    if (valid) {
        // Main loop: 4-deep manual unroll, front-batched ds loads (MLP=4).
        int i = tid;
        const int n4_main = n4 - 3 * 256; // last full-quad start bound
        for (; i < n4_main; i += 1024) {
            const int i0 = i, i1 = i + 256, i2 = i + 512, i3 = i + 768;
            const float d0 = __ldg(mrow + (i0 >> 2));
            const float d1 = __ldg(mrow + (i1 >> 2));
            const float d2 = __ldg(mrow + (i2 >> 2));
            const float d3 = __ldg(mrow + (i3 >> 2));
            float4 v0, v1, v2, v3;
            v0.x = fmaf(d0, Bv.x, A.x); v0.y = fmaf(d0, Bv.y, A.y);
            v0.z = fmaf(d0, Bv.z, A.z); v0.w = fmaf(d0, Bv.w, A.w);
            v1.x = fmaf(d1, Bv.x, A.x); v1.y = fmaf(d1, Bv.y, A.y);
            v1.z = fmaf(d1, Bv.z, A.z); v1.w = fmaf(d1, Bv.w, A.w);
            v2.x = fmaf(d2, Bv.x, A.x); v2.y = fmaf(d2, Bv.y, A.y);
            v2.z = fmaf(d2, Bv.z, A.z); v2.w = fmaf(d2, Bv.w, A.w);
            v3.x = fmaf(d3, Bv.x, A.x); v3.y = fmaf(d3, Bv.y, A.y);
            v3.z = fmaf(d3, Bv.z, A.z); v3.w = fmaf(d3, Bv.w, A.w);
            __stcs(o + i0, v0);
            __stcs(o + i1, v1);
            __stcs(o + i2, v2);
            __stcs(o + i3, v3);
        }
        // Remainder
        for (; i < n4; i += 256) {
            const float ds = __ldg(mrow + (i >> 2));
            float4 v;
            v.x = fmaf(ds, Bv.x, A.x); v.y = fmaf(ds, Bv.y, A.y);
            v.z = fmaf(ds, Bv.z, A.z); v.w = fmaf(ds, Bv.w, A.w);
            __stcs(o + i, v);
        }
    } else {
        int i = tid;
        const int n4_main = n4 - 3 * 256;
        for (; i < n4_main; i += 1024) {
            __stcs(o + i,       A);
            __stcs(o + i + 256, A);
            __stcs(o + i + 512, A);
            __stcs(o + i + 768, A);
        }
        for (; i < n4; i += 256) __stcs(o + i, A);
    }
}

// Generic fallback (any E divisible by 4)
__global__ void __launch_bounds__(256) embed_kernel_gen(
    const int*   __restrict__ traj_loc,
    const float* __restrict__ mat2,
    const float* __restrict__ vec,
    const int*   __restrict__ traj_len,
    const float* __restrict__ emb_sl,
    const float* __restrict__ emb_su,
    const float* __restrict__ emb_tl,
    const float* __restrict__ emb_tu,
    float*       __restrict__ out,
    int L, int LOC, int E)
{
    const int bl = blockIdx.x;
    const int b  = bl / L;
    const int l  = bl - b * L;

    const bool valid = (l < traj_len[b]);
    const int  m     = valid ? 1 : 0;
    const float t    = vec[bl];

    int row = traj_loc[bl] - 1;
    row = row < 0 ? 0 : (row > LOC - 1 ? LOC - 1 : row);

    const int EQ = E >> 2;
    const int q  = threadIdx.x % EQ;
    float4 A, Bv;
    compute_coeffs(emb_sl, emb_su, emb_tl, emb_tu, m, E, q, t, A, Bv);

    const float* __restrict__ mrow = mat2 + (size_t)row * LOC;
    float4* __restrict__ o = reinterpret_cast<float4*>(out + (size_t)bl * LOC * E);

    const int n4 = LOC * EQ;
    for (int i = threadIdx.x; i < n4; i += 256) {
        const float ds = valid ? __ldg(mrow + i / EQ) : 0.0f;
        float4 v;
        v.x = fmaf(ds, Bv.x, A.x); v.y = fmaf(ds, Bv.y, A.y);
        v.z = fmaf(ds, Bv.z, A.z); v.w = fmaf(ds, Bv.w, A.w);
        __stcs(o + i, v);
    }
}

extern "C" void kernel_launch(void* const* d_in, const int* in_sizes, int n_in,
                              void* d_out, int out_size)
{
    const int*   traj_loc = (const int*)  d_in[0];
    const float* mat2     = (const float*)d_in[1];
    const float* vec      = (const float*)d_in[2];
    const int*   traj_len = (const int*)  d_in[3];
    const float* emb_sl   = (const float*)d_in[4];
    const float* emb_su   = (const float*)d_in[5];
    const float* emb_tl   = (const float*)d_in[6];
    const float* emb_tu   = (const float*)d_in[7];

    const int BL  = in_sizes[0];
    const int B   = in_sizes[3];
    const int L   = BL / B;
    const int LOC = (int)(sqrt((double)in_sizes[1]) + 0.5);
    const int E   = in_sizes[4] / 2;

    if (E == 16) {
        embed_kernel_e16<<<BL, 256>>>(traj_loc, mat2, vec, traj_len,
                                      emb_sl, emb_su, emb_tl, emb_tu,
                                      (float*)d_out, L, LOC);
    } else {
        embed_kernel_gen<<<BL, 256>>>(traj_loc, mat2, vec, traj_len,
                                      emb_sl, emb_su, emb_tl, emb_tu,
                                      (float*)d_out, L, LOC, E);
    }
}

// round 5
// speedup vs baseline: 1.3777x; 1.0462x over previous
#include <cuda_runtime.h>
#include <math.h>

// out[b,l,c,e] = A[e] + ds * Bv[e]
//   ds = valid ? mat2[row, c] : 0
//   A[e]  = esl[m][e] + (etl[m][e]*(TU - t) + etu[m][e]*t) / TU
//   Bv[e] = (esu[m][e] - esl[m][e]) / SU
// SU=500, TU=3600 (SL=TL=0)

__device__ __forceinline__ void compute_coeffs(
    const float* __restrict__ emb_sl, const float* __restrict__ emb_su,
    const float* __restrict__ emb_tl, const float* __restrict__ emb_tu,
    int m, int E, int q, float t, float4& A, float4& Bv)
{
    const float4 esl = reinterpret_cast<const float4*>(emb_sl + m * E)[q];
    const float4 esu = reinterpret_cast<const float4*>(emb_su + m * E)[q];
    const float4 etl = reinterpret_cast<const float4*>(emb_tl + m * E)[q];
    const float4 etu = reinterpret_cast<const float4*>(emb_tu + m * E)[q];

    const float invS = 1.0f / 500.0f;
    const float invT = 1.0f / 3600.0f;
    const float TUv  = 3600.0f;

    A.x = fmaf(fmaf(etl.x, TUv - t, etu.x * t), invT, esl.x);
    A.y = fmaf(fmaf(etl.y, TUv - t, etu.y * t), invT, esl.y);
    A.z = fmaf(fmaf(etl.z, TUv - t, etu.z * t), invT, esl.z);
    A.w = fmaf(fmaf(etl.w, TUv - t, etu.w * t), invT, esl.w);
    Bv.x = (esu.x - esl.x) * invS;
    Bv.y = (esu.y - esl.y) * invS;
    Bv.z = (esu.z - esl.z) * invS;
    Bv.w = (esu.w - esl.w) * invS;
}

// Fast path: E == 16 (EQ = 4, c = i >> 2). mat2 row staged in dynamic smem.
__global__ void __launch_bounds__(256) embed_kernel_e16(
    const int*   __restrict__ traj_loc,
    const float* __restrict__ mat2,
    const float* __restrict__ vec,
    const int*   __restrict__ traj_len,
    const float* __restrict__ emb_sl,
    const float* __restrict__ emb_su,
    const float* __restrict__ emb_tl,
    const float* __restrict__ emb_tu,
    float*       __restrict__ out,
    int L, int LOC)
{
    extern __shared__ float srow[];   // LOC floats

    const int bl  = blockIdx.x;
    const int b   = bl / L;
    const int l   = bl - b * L;
    const int tid = threadIdx.x;

    const bool valid = (l < traj_len[b]);
    const int  m     = valid ? 1 : 0;
    const float t    = vec[bl];

    int row = traj_loc[bl] - 1;
    row = row < 0 ? 0 : (row > LOC - 1 ? LOC - 1 : row);

    const int q = tid & 3;
    float4 A, Bv;
    compute_coeffs(emb_sl, emb_su, emb_tl, emb_tu, m, 16, q, t, A, Bv);

    float4* __restrict__ o = reinterpret_cast<float4*>(out + (size_t)bl * LOC * 16);
    const int n4 = LOC * 4;                   // float4 elems per tile (8000)

    if (valid) {
        // Stage mat2 row into smem with float4 loads (LOC % 4 == 0 for LOC=2000;
        // scalar tail handles the general case).
        const float* __restrict__ mrow = mat2 + (size_t)row * LOC;
        const int nrow4 = LOC >> 2;
        const float4* __restrict__ mrow4 = reinterpret_cast<const float4*>(mrow);
        for (int i = tid; i < nrow4; i += 256)
            reinterpret_cast<float4*>(srow)[i] = __ldg(mrow4 + i);
        for (int i = (nrow4 << 2) + tid; i < LOC; i += 256)
            srow[i] = __ldg(mrow + i);
        __syncthreads();

        // Hot loop: LDS (broadcast) + 4 FMA + STG.128. No global-load stalls.
        int i = tid;
        const int n4_main = n4 - 3 * 256;
        for (; i < n4_main; i += 1024) {
            const float d0 = srow[(i)        >> 2];
            const float d1 = srow[(i + 256)  >> 2];
            const float d2 = srow[(i + 512)  >> 2];
            const float d3 = srow[(i + 768)  >> 2];
            float4 v0, v1, v2, v3;
            v0.x = fmaf(d0, Bv.x, A.x); v0.y = fmaf(d0, Bv.y, A.y);
            v0.z = fmaf(d0, Bv.z, A.z); v0.w = fmaf(d0, Bv.w, A.w);
            v1.x = fmaf(d1, Bv.x, A.x); v1.y = fmaf(d1, Bv.y, A.y);
            v1.z = fmaf(d1, Bv.z, A.z); v1.w = fmaf(d1, Bv.w, A.w);
            v2.x = fmaf(d2, Bv.x, A.x); v2.y = fmaf(d2, Bv.y, A.y);
            v2.z = fmaf(d2, Bv.z, A.z); v2.w = fmaf(d2, Bv.w, A.w);
            v3.x = fmaf(d3, Bv.x, A.x); v3.y = fmaf(d3, Bv.y, A.y);
            v3.z = fmaf(d3, Bv.z, A.z); v3.w = fmaf(d3, Bv.w, A.w);
            __stcs(o + i,       v0);
            __stcs(o + i + 256, v1);
            __stcs(o + i + 512, v2);
            __stcs(o + i + 768, v3);
        }
        for (; i < n4; i += 256) {
            const float ds = srow[i >> 2];
            float4 v;
            v.x = fmaf(ds, Bv.x, A.x); v.y = fmaf(ds, Bv.y, A.y);
            v.z = fmaf(ds, Bv.z, A.z); v.w = fmaf(ds, Bv.w, A.w);
            __stcs(o + i, v);
        }
    } else {
        int i = tid;
        const int n4_main = n4 - 3 * 256;
        for (; i < n4_main; i += 1024) {
            __stcs(o + i,       A);
            __stcs(o + i + 256, A);
            __stcs(o + i + 512, A);
            __stcs(o + i + 768, A);
        }
        for (; i < n4; i += 256) __stcs(o + i, A);
    }
}

// Generic fallback (any E divisible by 4)
__global__ void __launch_bounds__(256) embed_kernel_gen(
    const int*   __restrict__ traj_loc,
    const float* __restrict__ mat2,
    const float* __restrict__ vec,
    const int*   __restrict__ traj_len,
    const float* __restrict__ emb_sl,
    const float* __restrict__ emb_su,
    const float* __restrict__ emb_tl,
    const float* __restrict__ emb_tu,
    float*       __restrict__ out,
    int L, int LOC, int E)
{
    const int bl = blockIdx.x;
    const int b  = bl / L;
    const int l  = bl - b * L;

    const bool valid = (l < traj_len[b]);
    const int  m     = valid ? 1 : 0;
    const float t    = vec[bl];

    int row = traj_loc[bl] - 1;
    row = row < 0 ? 0 : (row > LOC - 1 ? LOC - 1 : row);

    const int EQ = E >> 2;
    const int q  = threadIdx.x % EQ;
    float4 A, Bv;
    compute_coeffs(emb_sl, emb_su, emb_tl, emb_tu, m, E, q, t, A, Bv);

    const float* __restrict__ mrow = mat2 + (size_t)row * LOC;
    float4* __restrict__ o = reinterpret_cast<float4*>(out + (size_t)bl * LOC * E);

    const int n4 = LOC * EQ;
    for (int i = threadIdx.x; i < n4; i += 256) {
        const float ds = valid ? __ldg(mrow + i / EQ) : 0.0f;
        float4 v;
        v.x = fmaf(ds, Bv.x, A.x); v.y = fmaf(ds, Bv.y, A.y);
        v.z = fmaf(ds, Bv.z, A.z); v.w = fmaf(ds, Bv.w, A.w);
        __stcs(o + i, v);
    }
}

extern "C" void kernel_launch(void* const* d_in, const int* in_sizes, int n_in,
                              void* d_out, int out_size)
{
    const int*   traj_loc = (const int*)  d_in[0];
    const float* mat2     = (const float*)d_in[1];
    const float* vec      = (const float*)d_in[2];
    const int*   traj_len = (const int*)  d_in[3];
    const float* emb_sl   = (const float*)d_in[4];
    const float* emb_su   = (const float*)d_in[5];
    const float* emb_tl   = (const float*)d_in[6];
    const float* emb_tu   = (const float*)d_in[7];

    const int BL  = in_sizes[0];
    const int B   = in_sizes[3];
    const int L   = BL / B;
    const int LOC = (int)(sqrt((double)in_sizes[1]) + 0.5);
    const int E   = in_sizes[4] / 2;

    const size_t smem = (size_t)LOC * sizeof(float);

    if (E == 16 && smem <= 100 * 1024) {
        embed_kernel_e16<<<BL, 256, smem>>>(traj_loc, mat2, vec, traj_len,
                                            emb_sl, emb_su, emb_tl, emb_tu,
                                            (float*)d_out, L, LOC);
    } else {
        embed_kernel_gen<<<BL, 256>>>(traj_loc, mat2, vec, traj_len,
                                      emb_sl, emb_su, emb_tl, emb_tu,
                                      (float*)d_out, L, LOC, E);
    }
}

// round 6
// speedup vs baseline: 1.4696x; 1.0667x over previous
#include <cuda_runtime.h>
#include <math.h>

// out[b,l,c,e] = A[e] + ds * Bv[e]
//   ds = valid ? mat2[row, c] : 0
//   A[e]  = esl[m][e] + (etl[m][e]*(TU - t) + etu[m][e]*t) / TU
//   Bv[e] = (esu[m][e] - esl[m][e]) / SU

#define SPLIT 4   // CTAs per (b,l) tile

__device__ __forceinline__ void compute_coeffs(
    const float* __restrict__ emb_sl, const float* __restrict__ emb_su,
    const float* __restrict__ emb_tl, const float* __restrict__ emb_tu,
    int m, int E, int q, float t, float4& A, float4& Bv)
{
    const float4 esl = reinterpret_cast<const float4*>(emb_sl + m * E)[q];
    const float4 esu = reinterpret_cast<const float4*>(emb_su + m * E)[q];
    const float4 etl = reinterpret_cast<const float4*>(emb_tl + m * E)[q];
    const float4 etu = reinterpret_cast<const float4*>(emb_tu + m * E)[q];

    const float invS = 1.0f / 500.0f;
    const float invT = 1.0f / 3600.0f;
    const float TUv  = 3600.0f;

    A.x = fmaf(fmaf(etl.x, TUv - t, etu.x * t), invT, esl.x);
    A.y = fmaf(fmaf(etl.y, TUv - t, etu.y * t), invT, esl.y);
    A.z = fmaf(fmaf(etl.z, TUv - t, etu.z * t), invT, esl.z);
    A.w = fmaf(fmaf(etl.w, TUv - t, etu.w * t), invT, esl.w);
    Bv.x = (esu.x - esl.x) * invS;
    Bv.y = (esu.y - esl.y) * invS;
    Bv.z = (esu.z - esl.z) * invS;
    Bv.w = (esu.w - esl.w) * invS;
}

// Fast path: E == 16. Each CTA handles 1/SPLIT of one (b,l) tile.
__global__ void __launch_bounds__(256, 6) embed_kernel_e16(
    const int*   __restrict__ traj_loc,
    const float* __restrict__ mat2,
    const float* __restrict__ vec,
    const int*   __restrict__ traj_len,
    const float* __restrict__ emb_sl,
    const float* __restrict__ emb_su,
    const float* __restrict__ emb_tl,
    const float* __restrict__ emb_tu,
    float*       __restrict__ out,
    int L, int LOC)
{
    extern __shared__ float srow[];   // staged slice of the mat2 row

    const int bid  = blockIdx.x;
    const int bl   = bid / SPLIT;
    const int half = bid - bl * SPLIT;
    const int b    = bl / L;
    const int l    = bl - b * L;
    const int tid  = threadIdx.x;

    const bool valid = (l < traj_len[b]);
    const int  m     = valid ? 1 : 0;
    const float t    = vec[bl];

    int row = traj_loc[bl] - 1;
    row = row < 0 ? 0 : (row > LOC - 1 ? LOC - 1 : row);

    const int q = tid & 3;
    float4 A, Bv;
    compute_coeffs(emb_sl, emb_su, emb_tl, emb_tu, m, 16, q, t, A, Bv);

    const int n4    = LOC * 4;                       // float4 elems per tile
    const int chunk = (n4 + SPLIT - 1) / SPLIT;
    const int start = half * chunk;
    const int end   = (start + chunk < n4) ? (start + chunk) : n4;

    float4* __restrict__ o = reinterpret_cast<float4*>(out + (size_t)bl * LOC * 16);

    if (valid) {
        // Stage the needed row slice: c in [c0, c1)
        const int c0 = start >> 2;
        const int c1 = ((end - 1) >> 2) + 1;
        const float* __restrict__ mrow = mat2 + (size_t)row * LOC;
        for (int c = c0 + tid; c < c1; c += 256)
            srow[c - c0] = __ldg(mrow + c);
        __syncthreads();

        int i = start + tid;
        const int end_main = end - 3 * 256;
        for (; i < end_main; i += 1024) {
            const float d0 = srow[((i)       >> 2) - c0];
            const float d1 = srow[((i + 256) >> 2) - c0];
            const float d2 = srow[((i + 512) >> 2) - c0];
            const float d3 = srow[((i + 768) >> 2) - c0];
            float4 v0, v1, v2, v3;
            v0.x = fmaf(d0, Bv.x, A.x); v0.y = fmaf(d0, Bv.y, A.y);
            v0.z = fmaf(d0, Bv.z, A.z); v0.w = fmaf(d0, Bv.w, A.w);
            v1.x = fmaf(d1, Bv.x, A.x); v1.y = fmaf(d1, Bv.y, A.y);
            v1.z = fmaf(d1, Bv.z, A.z); v1.w = fmaf(d1, Bv.w, A.w);
            v2.x = fmaf(d2, Bv.x, A.x); v2.y = fmaf(d2, Bv.y, A.y);
            v2.z = fmaf(d2, Bv.z, A.z); v2.w = fmaf(d2, Bv.w, A.w);
            v3.x = fmaf(d3, Bv.x, A.x); v3.y = fmaf(d3, Bv.y, A.y);
            v3.z = fmaf(d3, Bv.z, A.z); v3.w = fmaf(d3, Bv.w, A.w);
            __stcs(o + i,       v0);
            __stcs(o + i + 256, v1);
            __stcs(o + i + 512, v2);
            __stcs(o + i + 768, v3);
        }
        for (; i < end; i += 256) {
            const float ds = srow[(i >> 2) - c0];
            float4 v;
            v.x = fmaf(ds, Bv.x, A.x); v.y = fmaf(ds, Bv.y, A.y);
            v.z = fmaf(ds, Bv.z, A.z); v.w = fmaf(ds, Bv.w, A.w);
            __stcs(o + i, v);
        }
    } else {
        int i = start + tid;
        const int end_main = end - 3 * 256;
        for (; i < end_main; i += 1024) {
            __stcs(o + i,       A);
            __stcs(o + i + 256, A);
            __stcs(o + i + 512, A);
            __stcs(o + i + 768, A);
        }
        for (; i < end; i += 256) __stcs(o + i, A);
    }
}

// Generic fallback (any E divisible by 4)
__global__ void __launch_bounds__(256) embed_kernel_gen(
    const int*   __restrict__ traj_loc,
    const float* __restrict__ mat2,
    const float* __restrict__ vec,
    const int*   __restrict__ traj_len,
    const float* __restrict__ emb_sl,
    const float* __restrict__ emb_su,
    const float* __restrict__ emb_tl,
    const float* __restrict__ emb_tu,
    float*       __restrict__ out,
    int L, int LOC, int E)
{
    const int bl = blockIdx.x;
    const int b  = bl / L;
    const int l  = bl - b * L;

    const bool valid = (l < traj_len[b]);
    const int  m     = valid ? 1 : 0;
    const float t    = vec[bl];

    int row = traj_loc[bl] - 1;
    row = row < 0 ? 0 : (row > LOC - 1 ? LOC - 1 : row);

    const int EQ = E >> 2;
    const int q  = threadIdx.x % EQ;
    float4 A, Bv;
    compute_coeffs(emb_sl, emb_su, emb_tl, emb_tu, m, E, q, t, A, Bv);

    const float* __restrict__ mrow = mat2 + (size_t)row * LOC;
    float4* __restrict__ o = reinterpret_cast<float4*>(out + (size_t)bl * LOC * E);

    const int n4 = LOC * EQ;
    for (int i = threadIdx.x; i < n4; i += 256) {
        const float ds = valid ? __ldg(mrow + i / EQ) : 0.0f;
        float4 v;
        v.x = fmaf(ds, Bv.x, A.x); v.y = fmaf(ds, Bv.y, A.y);
        v.z = fmaf(ds, Bv.z, A.z); v.w = fmaf(ds, Bv.w, A.w);
        __stcs(o + i, v);
    }
}

extern "C" void kernel_launch(void* const* d_in, const int* in_sizes, int n_in,
                              void* d_out, int out_size)
{
    const int*   traj_loc = (const int*)  d_in[0];
    const float* mat2     = (const float*)d_in[1];
    const float* vec      = (const float*)d_in[2];
    const int*   traj_len = (const int*)  d_in[3];
    const float* emb_sl   = (const float*)d_in[4];
    const float* emb_su   = (const float*)d_in[5];
    const float* emb_tl   = (const float*)d_in[6];
    const float* emb_tu   = (const float*)d_in[7];

    const int BL  = in_sizes[0];
    const int B   = in_sizes[3];
    const int L   = BL / B;
    const int LOC = (int)(sqrt((double)in_sizes[1]) + 0.5);
    const int E   = in_sizes[4] / 2;

    // smem: staged row slice = ceil(LOC/SPLIT)+4 floats
    const int slice  = (LOC + SPLIT - 1) / SPLIT + 4;
    const size_t smem = (size_t)slice * sizeof(float);

    if (E == 16 && smem <= 32 * 1024) {
        embed_kernel_e16<<<BL * SPLIT, 256, smem>>>(traj_loc, mat2, vec, traj_len,
                                                    emb_sl, emb_su, emb_tl, emb_tu,
                                                    (float*)d_out, L, LOC);
    } else {
        embed_kernel_gen<<<BL, 256>>>(traj_loc, mat2, vec, traj_len,
                                      emb_sl, emb_su, emb_tl, emb_tu,
                                      (float*)d_out, L, LOC, E);
    }
}